// round 3
// baseline (speedup 1.0000x reference)
#include <cuda_runtime.h>
#include <cuda_bf16.h>
#include <cstdint>
#include <cstddef>

#define NN 100000
#define EE 1600000
#define FF 128
#define HH 128
#define LL 4
#define SS 10000
#define GG 256
#define CC 10

// ---------------- scratch (device globals; no allocation allowed) ----------------
__device__ int   d_deg[NN];
__device__ int   d_off[NN + 1];
__device__ int   d_cursor[NN];
__device__ int   d_csr[EE];
__device__ float d_t[(size_t)NN * HH];
__device__ float d_feat[(size_t)NN * LL * HH];   // raw z per layer; BN applied on read
__device__ float d_stats[2 * HH];
__device__ float d_sc1[HH];
__device__ float d_sh1[HH];
__device__ float d_pscale[LL * HH];
__device__ float d_pshift[LL * HH];
__device__ int   d_suboff[SS + 1];
__device__ int   d_gphoff[GG + 1];
__device__ float d_sub[(size_t)SS * LL * HH];
__device__ float d_gph[(size_t)GG * LL * HH];
__device__ __nv_bfloat16 d_Whi[8 * 128 * 128];   // mat = l*2 (W1), l*2+1 (W2)
__device__ __nv_bfloat16 d_Wlo[8 * 128 * 128];

// ---------------- smem layout for mm kernel ----------------
// bf16 tiles [128 rows][136 cols] (stride 136 => 272B rows, conflict-free LDSM)
#define TST   136
#define TBYTES (128 * TST * 2)     // 34816
#define SM_AH 0
#define SM_AL (SM_AH + TBYTES)
#define SM_WH (SM_AL + TBYTES)
#define SM_WL (SM_WH + TBYTES)
#define MM_SMEM (SM_WL + TBYTES)   // 139264
#define YS_STRIDE 129              // f32 staging stride (reuses A region)

__device__ __forceinline__ uint32_t smem_u32(const void* p) {
    uint32_t a;
    asm("{ .reg .u64 t; cvta.to.shared.u64 t, %1; cvt.u32.u64 %0, t; }" : "=r"(a) : "l"(p));
    return a;
}
__device__ __forceinline__ void ldsm_x4(uint32_t* a, uint32_t addr) {
    asm volatile("ldmatrix.sync.aligned.m8n8.x4.shared.b16 {%0,%1,%2,%3}, [%4];"
        : "=r"(a[0]), "=r"(a[1]), "=r"(a[2]), "=r"(a[3]) : "r"(addr));
}
__device__ __forceinline__ void ldsm_x2(uint32_t* b, uint32_t addr) {
    asm volatile("ldmatrix.sync.aligned.m8n8.x2.shared.b16 {%0,%1}, [%2];"
        : "=r"(b[0]), "=r"(b[1]) : "r"(addr));
}
__device__ __forceinline__ void mma_bf16(float* c, const uint32_t* a, const uint32_t* b) {
    asm volatile("mma.sync.aligned.m16n8k16.row.col.f32.bf16.bf16.f32 "
        "{%0,%1,%2,%3}, {%4,%5,%6,%7}, {%8,%9}, {%0,%1,%2,%3};"
        : "+f"(c[0]), "+f"(c[1]), "+f"(c[2]), "+f"(c[3])
        : "r"(a[0]), "r"(a[1]), "r"(a[2]), "r"(a[3]), "r"(b[0]), "r"(b[1]));
}

__device__ __forceinline__ void cvt_split4(float4 v, uint2& hi, uint2& lo) {
    __nv_bfloat16 h0 = __float2bfloat16(v.x), h1 = __float2bfloat16(v.y);
    __nv_bfloat16 h2 = __float2bfloat16(v.z), h3 = __float2bfloat16(v.w);
    __nv_bfloat16 l0 = __float2bfloat16(v.x - __bfloat162float(h0));
    __nv_bfloat16 l1 = __float2bfloat16(v.y - __bfloat162float(h1));
    __nv_bfloat16 l2 = __float2bfloat16(v.z - __bfloat162float(h2));
    __nv_bfloat16 l3 = __float2bfloat16(v.w - __bfloat162float(h3));
    hi.x = (uint32_t)__bfloat16_as_ushort(h0) | ((uint32_t)__bfloat16_as_ushort(h1) << 16);
    hi.y = (uint32_t)__bfloat16_as_ushort(h2) | ((uint32_t)__bfloat16_as_ushort(h3) << 16);
    lo.x = (uint32_t)__bfloat16_as_ushort(l0) | ((uint32_t)__bfloat16_as_ushort(l1) << 16);
    lo.y = (uint32_t)__bfloat16_as_ushort(l2) | ((uint32_t)__bfloat16_as_ushort(l3) << 16);
}

template <bool HAS_T>
__device__ __forceinline__ float4 act4(float4 v, float4 sc, float4 sh) {
    if (HAS_T) {
        v.x = fmaxf(fmaf(v.x, sc.x, sh.x), 0.f);
        v.y = fmaxf(fmaf(v.y, sc.y, sh.y), 0.f);
        v.z = fmaxf(fmaf(v.z, sc.z, sh.z), 0.f);
        v.w = fmaxf(fmaf(v.w, sc.w, sh.w), 0.f);
    }
    return v;
}

// Y[tile] = A[tile,128] @ W^T (bf16x3 split on tensor cores) + bias, fused stats.
// MODE 0: A row = GIN aggregate of act(input) over CSR; MODE 1: A row = act(Ain row).
template <int MODE, bool HAS_T>
__global__ void __launch_bounds__(256, 1)
mm_hmma_kernel(const float* __restrict__ Ain, int lda,
               const float* __restrict__ tsc, const float* __restrict__ tsh,
               const float* __restrict__ eps_ptr, int layer,
               const __nv_bfloat16* __restrict__ Whi, const __nv_bfloat16* __restrict__ Wlo,
               const float* __restrict__ bias,
               float* __restrict__ Y, int ldy) {
    extern __shared__ char smem[];
    uint32_t sb = smem_u32(smem);
    int tid = threadIdx.x, wid = tid >> 5, lane = tid & 31;
    int row0 = blockIdx.x * 128;

    // ---- W hi/lo -> smem (rows n, cols k, stride 136) ----
#pragma unroll
    for (int i = tid; i < 128 * 16; i += 256) {
        int r = i >> 4, c8 = (i & 15) * 8;
        uint32_t dsto = (uint32_t)(r * (TST * 2) + c8 * 2);
        *(uint4*)(smem + SM_WH + dsto) = *(const uint4*)&Whi[r * 128 + c8];
        *(uint4*)(smem + SM_WL + dsto) = *(const uint4*)&Wlo[r * 128 + c8];
    }

    // ---- produce A hi/lo in smem ----
    if (MODE == 0) {
        float e = 1.0f + eps_ptr[layer];
        float4 sc4 = make_float4(1.f, 0.f, 0.f, 0.f), sh4 = sc4;
        if (HAS_T) {
            sc4 = *(const float4*)&tsc[lane * 4];
            sh4 = *(const float4*)&tsh[lane * 4];
        }
        int nl = wid;
#pragma unroll 1
        for (int it = 0; it < 16; ++it, nl += 8) {
            int gn = row0 + nl;
            float4 acc = make_float4(0.f, 0.f, 0.f, 0.f);
            if (gn < NN) {
                int js = d_off[gn], je = d_off[gn + 1];
                int j = js;
#pragma unroll 1
                for (; j + 8 <= je; j += 8) {
                    int ii[8];
#pragma unroll
                    for (int q = 0; q < 8; q++) ii[q] = d_csr[j + q];
                    float4 v[8];
#pragma unroll
                    for (int q = 0; q < 8; q++)
                        v[q] = act4<HAS_T>(*(const float4*)&Ain[(size_t)ii[q] * lda + lane * 4], sc4, sh4);
#pragma unroll
                    for (int q = 0; q < 8; q++) {
                        acc.x += v[q].x; acc.y += v[q].y; acc.z += v[q].z; acc.w += v[q].w;
                    }
                }
                for (; j < je; ++j) {
                    int i0 = d_csr[j];
                    float4 v0 = act4<HAS_T>(*(const float4*)&Ain[(size_t)i0 * lda + lane * 4], sc4, sh4);
                    acc.x += v0.x; acc.y += v0.y; acc.z += v0.z; acc.w += v0.w;
                }
                float4 xs = act4<HAS_T>(*(const float4*)&Ain[(size_t)gn * lda + lane * 4], sc4, sh4);
                acc.x = fmaf(e, xs.x, acc.x); acc.y = fmaf(e, xs.y, acc.y);
                acc.z = fmaf(e, xs.z, acc.z); acc.w = fmaf(e, xs.w, acc.w);
            }
            uint2 hi, lo;
            cvt_split4(acc, hi, lo);
            uint32_t dsto = (uint32_t)(nl * (TST * 2) + lane * 8);
            *(uint2*)(smem + SM_AH + dsto) = hi;
            *(uint2*)(smem + SM_AL + dsto) = lo;
        }
    } else {
#pragma unroll 1
        for (int i = tid; i < 128 * 32; i += 256) {
            int r = i >> 5, c4 = (i & 31) * 4;
            int gr = row0 + r;
            float4 v = make_float4(0.f, 0.f, 0.f, 0.f);
            if (gr < NN) {
                float4 sc4 = *(const float4*)&tsc[c4];
                float4 sh4 = *(const float4*)&tsh[c4];
                v = act4<true>(*(const float4*)&Ain[(size_t)gr * lda + c4], sc4, sh4);
            }
            uint2 hi, lo;
            cvt_split4(v, hi, lo);
            uint32_t dsto = (uint32_t)(r * (TST * 2) + c4 * 2);
            *(uint2*)(smem + SM_AH + dsto) = hi;
            *(uint2*)(smem + SM_AL + dsto) = lo;
        }
    }
    __syncthreads();

    // ---- load A fragments for this warp's 16 rows (all K) ----
    uint32_t ah[32], al[32];
    {
        int g = lane & 7, q = lane >> 3;
        uint32_t aaddr = sb + SM_AH + (uint32_t)((16 * wid + g + (q & 1) * 8) * (TST * 2) + (q >> 1) * 16);
#pragma unroll
        for (int k8 = 0; k8 < 8; k8++) {
            ldsm_x4(&ah[k8 * 4], aaddr + k8 * 32);
            ldsm_x4(&al[k8 * 4], aaddr + k8 * 32 + (SM_AL - SM_AH));
        }
    }
    __syncthreads();  // A smem region now reusable as Ys staging

    // ---- MMA: D = Ah*Wh + Al*Wh + Ah*Wl, write each n-tile to staging ----
    float* Ys = (float*)smem;
    {
        int g = lane & 7, q = (lane >> 3) & 1;
        uint32_t wbase = sb + SM_WH + (uint32_t)(g * (TST * 2) + q * 16);
        int gid = lane >> 2, ctib = lane & 3;
#pragma unroll 1
        for (int nt = 0; nt < 16; nt++) {
            float c[4] = {0.f, 0.f, 0.f, 0.f};
#pragma unroll
            for (int k8 = 0; k8 < 8; k8++) {
                uint32_t wa = wbase + (uint32_t)(nt * 8 * (TST * 2) + k8 * 32);
                uint32_t bh[2], bl[2];
                ldsm_x2(bh, wa);
                ldsm_x2(bl, wa + (SM_WL - SM_WH));
                mma_bf16(c, &ah[k8 * 4], bh);
                mma_bf16(c, &al[k8 * 4], bh);
                mma_bf16(c, &ah[k8 * 4], bl);
            }
            int col = nt * 8 + 2 * ctib;
            int r0w = 16 * wid + gid;
            Ys[r0w * YS_STRIDE + col] = c[0];
            Ys[r0w * YS_STRIDE + col + 1] = c[1];
            Ys[(r0w + 8) * YS_STRIDE + col] = c[2];
            Ys[(r0w + 8) * YS_STRIDE + col + 1] = c[3];
        }
    }
    __syncthreads();

    // ---- epilogue: bias + coalesced global store + fused BN stats ----
    {
        int c = tid & 127;
        float b = bias[c];
        float s = 0.f, s2 = 0.f;
        for (int rr = (tid >> 7); rr < 128; rr += 2) {
            int gr = row0 + rr;
            if (gr >= NN) break;
            float v = Ys[rr * YS_STRIDE + c] + b;
            s += v;
            s2 = fmaf(v, v, s2);
            Y[(size_t)gr * ldy + c] = v;
        }
        atomicAdd(&d_stats[c], s);
        atomicAdd(&d_stats[HH + c], s2);
    }
}

// ---------------- W conversion ----------------
__global__ void convw_kernel(const float* __restrict__ W1, const float* __restrict__ W2) {
    int i = blockIdx.x * 256 + threadIdx.x;
    if (i >= 8 * 16384) return;
    int mat = i >> 14, e = i & 16383, l = mat >> 1;
    float v = (mat & 1) ? W2[(size_t)l * 16384 + e] : W1[(size_t)l * 16384 + e];
    __nv_bfloat16 h = __float2bfloat16(v);
    d_Whi[i] = h;
    d_Wlo[i] = __float2bfloat16(v - __bfloat162float(h));
}

// ---------------- CSR build ----------------
__global__ void zero_deg_kernel() {
    int i = blockIdx.x * blockDim.x + threadIdx.x;
    if (i < NN) d_deg[i] = 0;
}
__global__ void count_kernel(const int* __restrict__ dst) {
    int i = blockIdx.x * blockDim.x + threadIdx.x;
    if (i < EE) atomicAdd(&d_deg[dst[i]], 1);
}
__global__ void scan_kernel() {
    __shared__ int wsum[32];
    __shared__ int carry_s;
    int t = threadIdx.x, lane = t & 31, w = t >> 5;
    if (t == 0) carry_s = 0;
    __syncthreads();
    for (int base = 0; base < NN; base += 1024) {
        int carry = carry_s;
        int idx = base + t;
        int v = (idx < NN) ? d_deg[idx] : 0;
        int x = v;
#pragma unroll
        for (int d = 1; d < 32; d <<= 1) {
            int y = __shfl_up_sync(0xffffffffu, x, d);
            if (lane >= d) x += y;
        }
        if (lane == 31) wsum[w] = x;
        __syncthreads();
        if (w == 0) {
            int s = wsum[lane];
#pragma unroll
            for (int d = 1; d < 32; d <<= 1) {
                int y = __shfl_up_sync(0xffffffffu, s, d);
                if (lane >= d) s += y;
            }
            wsum[lane] = s;
        }
        __syncthreads();
        int woff = (w > 0) ? wsum[w - 1] : 0;
        int excl = carry + woff + x - v;
        if (idx < NN) { d_off[idx] = excl; d_cursor[idx] = excl; }
        int tot = wsum[31];
        __syncthreads();
        if (t == 0) carry_s = carry + tot;
        __syncthreads();
    }
    if (threadIdx.x == 0) d_off[NN] = carry_s;
}
__global__ void fill_kernel(const int* __restrict__ src, const int* __restrict__ dst) {
    int i = blockIdx.x * blockDim.x + threadIdx.x;
    if (i < EE) {
        int p = atomicAdd(&d_cursor[dst[i]], 1);
        d_csr[p] = src[i];
    }
}

// ---------------- BN finalize (zeroes stats for next use) ----------------
__global__ void zero_stats_kernel() { d_stats[threadIdx.x] = 0.f; }

__global__ void bn_final_kernel(const float* __restrict__ gamma, const float* __restrict__ beta,
                                float* __restrict__ osc, float* __restrict__ osh) {
    int c = threadIdx.x;
    const float inv_n = 1.0f / (float)NN;
    float mu = d_stats[c] * inv_n;
    float var = fmaf(-mu, mu, d_stats[HH + c] * inv_n);
    float rinv = rsqrtf(var + 1e-5f);
    float sc = rinv * gamma[c];
    osc[c] = sc;
    osh[c] = fmaf(-mu, sc, beta[c]);
    d_stats[c] = 0.f;
    d_stats[HH + c] = 0.f;
}

// ---------------- pooling ----------------
__global__ void lower_bound_kernel(const int* __restrict__ seg, int n, int* __restrict__ out, int nseg) {
    int s = blockIdx.x * blockDim.x + threadIdx.x;
    if (s > nseg) return;
    int lo = 0, hi = n;
    while (lo < hi) {
        int mid = (lo + hi) >> 1;
        if (seg[mid] < s) lo = mid + 1; else hi = mid;
    }
    out[s] = lo;
}

__global__ void segmean_kernel(const float* __restrict__ in, const int* __restrict__ off,
                               float* __restrict__ out,
                               const float* __restrict__ tsc, const float* __restrict__ tsh) {
    int s = blockIdx.x, t = threadIdx.x;  // 128 threads, float4 each (512 cols)
    int r0 = off[s], r1 = off[s + 1];
    float4 sc4 = make_float4(1.f, 0.f, 0.f, 0.f), sh4 = sc4;
    bool hasT = (tsc != nullptr);
    if (hasT) { sc4 = *(const float4*)&tsc[t * 4]; sh4 = *(const float4*)&tsh[t * 4]; }
    float4 acc = make_float4(0.f, 0.f, 0.f, 0.f);
    for (int r = r0; r < r1; r++) {
        float4 v = *(const float4*)&in[(size_t)r * (LL * HH) + t * 4];
        if (hasT) {
            v.x = fmaxf(fmaf(v.x, sc4.x, sh4.x), 0.f);
            v.y = fmaxf(fmaf(v.y, sc4.y, sh4.y), 0.f);
            v.z = fmaxf(fmaf(v.z, sc4.z, sh4.z), 0.f);
            v.w = fmaxf(fmaf(v.w, sc4.w, sh4.w), 0.f);
        }
        acc.x += v.x; acc.y += v.y; acc.z += v.z; acc.w += v.w;
    }
    float inv = 1.0f / fmaxf((float)(r1 - r0), 1.0f);
    float4 o = make_float4(acc.x * inv, acc.y * inv, acc.z * inv, acc.w * inv);
    *(float4*)&out[(size_t)s * (LL * HH) + t * 4] = o;
}

// ---------------- head ----------------
__global__ void head_kernel(const float* __restrict__ gph,
                            const float* __restrict__ w1, const float* __restrict__ bb1,
                            const float* __restrict__ w2, const float* __restrict__ bb2,
                            float* __restrict__ out) {
    __shared__ float grow[LL * HH];
    __shared__ float hbuf[HH];
    __shared__ float obuf[CC];
    int g = blockIdx.x, t = threadIdx.x;
    for (int i = t; i < LL * HH; i += 128) grow[i] = gph[(size_t)g * (LL * HH) + i];
    __syncthreads();
    float acc = bb1[t];
#pragma unroll 8
    for (int k = 0; k < LL * HH; k++) acc = fmaf(grow[k], w1[(size_t)t * (LL * HH) + k], acc);
    hbuf[t] = fmaxf(acc, 0.f);
    __syncthreads();
    if (t < CC) {
        float a = bb2[t];
#pragma unroll 8
        for (int k = 0; k < HH; k++) a = fmaf(hbuf[k], w2[t * HH + k], a);
        obuf[t] = a;
    }
    __syncthreads();
    if (t == 0) {
        float m = obuf[0];
#pragma unroll
        for (int j = 1; j < CC; j++) m = fmaxf(m, obuf[j]);
        float se = 0.f;
#pragma unroll
        for (int j = 0; j < CC; j++) se += expf(obuf[j] - m);
        float lse = m + logf(se);
#pragma unroll
        for (int j = 0; j < CC; j++) out[g * CC + j] = obuf[j] - lse;
    }
}

// ---------------- launcher ----------------
extern "C" void kernel_launch(void* const* d_in, const int* in_sizes, int n_in,
                              void* d_out, int out_size) {
    const float* x     = (const float*)d_in[0];
    const int*   ei    = (const int*)d_in[1];
    const int*   n2s   = (const int*)d_in[2];
    const int*   s2g   = (const int*)d_in[3];
    const float* W1    = (const float*)d_in[4];
    const float* b1    = (const float*)d_in[5];
    const float* g1    = (const float*)d_in[6];
    const float* be1   = (const float*)d_in[7];
    const float* W2    = (const float*)d_in[8];
    const float* b2    = (const float*)d_in[9];
    const float* g2    = (const float*)d_in[10];
    const float* be2   = (const float*)d_in[11];
    const float* eps   = (const float*)d_in[12];
    const float* lin1W = (const float*)d_in[13];
    const float* lin1b = (const float*)d_in[14];
    const float* lin2W = (const float*)d_in[15];
    const float* lin2b = (const float*)d_in[16];
    float* out = (float*)d_out;

    void* p;
    cudaGetSymbolAddress(&p, d_t);      float* tp      = (float*)p;
    cudaGetSymbolAddress(&p, d_feat);   float* featp   = (float*)p;
    cudaGetSymbolAddress(&p, d_sc1);    float* sc1p    = (float*)p;
    cudaGetSymbolAddress(&p, d_sh1);    float* sh1p    = (float*)p;
    cudaGetSymbolAddress(&p, d_pscale); float* pscp    = (float*)p;
    cudaGetSymbolAddress(&p, d_pshift); float* pshp    = (float*)p;
    cudaGetSymbolAddress(&p, d_sub);    float* subp    = (float*)p;
    cudaGetSymbolAddress(&p, d_gph);    float* gphp    = (float*)p;
    cudaGetSymbolAddress(&p, d_suboff); int* suboffp   = (int*)p;
    cudaGetSymbolAddress(&p, d_gphoff); int* gphoffp   = (int*)p;
    cudaGetSymbolAddress(&p, d_Whi);    __nv_bfloat16* whip = (__nv_bfloat16*)p;
    cudaGetSymbolAddress(&p, d_Wlo);    __nv_bfloat16* wlop = (__nv_bfloat16*)p;

    cudaFuncSetAttribute(mm_hmma_kernel<0, false>, cudaFuncAttributeMaxDynamicSharedMemorySize, MM_SMEM);
    cudaFuncSetAttribute(mm_hmma_kernel<0, true>,  cudaFuncAttributeMaxDynamicSharedMemorySize, MM_SMEM);
    cudaFuncSetAttribute(mm_hmma_kernel<1, true>,  cudaFuncAttributeMaxDynamicSharedMemorySize, MM_SMEM);

    const int* src = ei;
    const int* dst = ei + EE;

    zero_stats_kernel<<<1, 2 * HH>>>();
    convw_kernel<<<(8 * 16384 + 255) / 256, 256>>>(W1, W2);

    zero_deg_kernel<<<(NN + 255) / 256, 256>>>();
    count_kernel<<<(EE + 255) / 256, 256>>>(dst);
    scan_kernel<<<1, 1024>>>();
    fill_kernel<<<(EE + 255) / 256, 256>>>(src, dst);

    const int tiles = (NN + 127) / 128;
    for (int l = 0; l < LL; l++) {
        const __nv_bfloat16* whi1 = whip + (size_t)(l * 2) * 16384;
        const __nv_bfloat16* wlo1 = wlop + (size_t)(l * 2) * 16384;
        const __nv_bfloat16* whi2 = whip + (size_t)(l * 2 + 1) * 16384;
        const __nv_bfloat16* wlo2 = wlop + (size_t)(l * 2 + 1) * 16384;

        if (l == 0) {
            mm_hmma_kernel<0, false><<<tiles, 256, MM_SMEM>>>(
                x, FF, nullptr, nullptr, eps, 0, whi1, wlo1, b1 + (size_t)l * HH, tp, HH);
        } else {
            mm_hmma_kernel<0, true><<<tiles, 256, MM_SMEM>>>(
                featp + (size_t)(l - 1) * HH, LL * HH,
                pscp + (size_t)(l - 1) * HH, pshp + (size_t)(l - 1) * HH,
                eps, l, whi1, wlo1, b1 + (size_t)l * HH, tp, HH);
        }
        bn_final_kernel<<<1, HH>>>(g1 + (size_t)l * HH, be1 + (size_t)l * HH, sc1p, sh1p);

        mm_hmma_kernel<1, true><<<tiles, 256, MM_SMEM>>>(
            tp, HH, sc1p, sh1p, nullptr, 0,
            whi2, wlo2, b2 + (size_t)l * HH, featp + (size_t)l * HH, LL * HH);
        bn_final_kernel<<<1, HH>>>(g2 + (size_t)l * HH, be2 + (size_t)l * HH,
                                   pscp + (size_t)l * HH, pshp + (size_t)l * HH);
    }

    lower_bound_kernel<<<(SS + 1 + 255) / 256, 256>>>(n2s, NN, suboffp, SS);
    lower_bound_kernel<<<(GG + 1 + 255) / 256, 256>>>(s2g, SS, gphoffp, GG);
    segmean_kernel<<<SS, 128>>>(featp, suboffp, subp, pscp, pshp);
    segmean_kernel<<<GG, 128>>>(subp, gphoffp, gphp, nullptr, nullptr);

    head_kernel<<<GG, 128>>>(gphp, lin1W, lin1b, lin2W, lin2b, out);
}

// round 4
// speedup vs baseline: 1.2610x; 1.2610x over previous
#include <cuda_runtime.h>
#include <cuda_bf16.h>
#include <cstdint>
#include <cstddef>

#define NN 100000
#define EE 1600000
#define FF 128
#define HH 128
#define LL 4
#define SS 10000
#define GG 256
#define CC 10

// ---------------- scratch (device globals; no allocation allowed) ----------------
__device__ int   d_deg[NN];
__device__ int   d_off[NN + 1];
__device__ int   d_cursor[NN];
__device__ int   d_csr[EE];
__device__ float d_u[(size_t)NN * HH];
__device__ float d_t[(size_t)NN * HH];
__device__ float d_feat[(size_t)NN * LL * HH];   // raw z per layer; BN applied on read
__device__ float d_stats[2 * HH];
__device__ float d_sc1[HH];
__device__ float d_sh1[HH];
__device__ float d_pscale[LL * HH];
__device__ float d_pshift[LL * HH];
__device__ int   d_suboff[SS + 1];
__device__ int   d_gphoff[GG + 1];
__device__ float d_sub[(size_t)SS * LL * HH];
__device__ float d_gph[(size_t)GG * LL * HH];
__device__ __nv_bfloat16 d_Whi[8 * 128 * 128];   // mat = l*2 (W1), l*2+1 (W2)
__device__ __nv_bfloat16 d_Wlo[8 * 128 * 128];

// ---------------- smem layout for mm kernel ----------------
#define TST   136
#define TBYTES (128 * TST * 2)     // 34816
#define SM_AH 0
#define SM_AL (SM_AH + TBYTES)
#define SM_WH (SM_AL + TBYTES)
#define SM_WL (SM_WH + TBYTES)
#define MM_SMEM (SM_WL + TBYTES)   // 139264
#define YS_STRIDE 129

__device__ __forceinline__ uint32_t smem_u32(const void* p) {
    uint32_t a;
    asm("{ .reg .u64 t; cvta.to.shared.u64 t, %1; cvt.u32.u64 %0, t; }" : "=r"(a) : "l"(p));
    return a;
}
__device__ __forceinline__ void ldsm_x4(uint32_t* a, uint32_t addr) {
    asm volatile("ldmatrix.sync.aligned.m8n8.x4.shared.b16 {%0,%1,%2,%3}, [%4];"
        : "=r"(a[0]), "=r"(a[1]), "=r"(a[2]), "=r"(a[3]) : "r"(addr));
}
__device__ __forceinline__ void ldsm_x2(uint32_t* b, uint32_t addr) {
    asm volatile("ldmatrix.sync.aligned.m8n8.x2.shared.b16 {%0,%1}, [%2];"
        : "=r"(b[0]), "=r"(b[1]) : "r"(addr));
}
__device__ __forceinline__ void mma_bf16(float* c, const uint32_t* a, const uint32_t* b) {
    asm volatile("mma.sync.aligned.m16n8k16.row.col.f32.bf16.bf16.f32 "
        "{%0,%1,%2,%3}, {%4,%5,%6,%7}, {%8,%9}, {%0,%1,%2,%3};"
        : "+f"(c[0]), "+f"(c[1]), "+f"(c[2]), "+f"(c[3])
        : "r"(a[0]), "r"(a[1]), "r"(a[2]), "r"(a[3]), "r"(b[0]), "r"(b[1]));
}

__device__ __forceinline__ void cvt_split4(float4 v, uint2& hi, uint2& lo) {
    __nv_bfloat16 h0 = __float2bfloat16(v.x), h1 = __float2bfloat16(v.y);
    __nv_bfloat16 h2 = __float2bfloat16(v.z), h3 = __float2bfloat16(v.w);
    __nv_bfloat16 l0 = __float2bfloat16(v.x - __bfloat162float(h0));
    __nv_bfloat16 l1 = __float2bfloat16(v.y - __bfloat162float(h1));
    __nv_bfloat16 l2 = __float2bfloat16(v.z - __bfloat162float(h2));
    __nv_bfloat16 l3 = __float2bfloat16(v.w - __bfloat162float(h3));
    hi.x = (uint32_t)__bfloat16_as_ushort(h0) | ((uint32_t)__bfloat16_as_ushort(h1) << 16);
    hi.y = (uint32_t)__bfloat16_as_ushort(h2) | ((uint32_t)__bfloat16_as_ushort(h3) << 16);
    lo.x = (uint32_t)__bfloat16_as_ushort(l0) | ((uint32_t)__bfloat16_as_ushort(l1) << 16);
    lo.y = (uint32_t)__bfloat16_as_ushort(l2) | ((uint32_t)__bfloat16_as_ushort(l3) << 16);
}

template <bool HAS_T>
__device__ __forceinline__ float4 act4(float4 v, float4 sc, float4 sh) {
    if (HAS_T) {
        v.x = fmaxf(fmaf(v.x, sc.x, sh.x), 0.f);
        v.y = fmaxf(fmaf(v.y, sc.y, sh.y), 0.f);
        v.z = fmaxf(fmaf(v.z, sc.z, sh.z), 0.f);
        v.w = fmaxf(fmaf(v.w, sc.w, sh.w), 0.f);
    }
    return v;
}

// ---------------- aggregation: u = (1+eps)*act(x) + sum_{nbr} act(x) ----------------
template <bool HAS_T>
__global__ void agg_kernel(const float* __restrict__ xin, int ldx,
                           const float* __restrict__ tsc, const float* __restrict__ tsh,
                           const float* __restrict__ eps_ptr, int layer,
                           float* __restrict__ u) {
    int node = blockIdx.x * 8 + (threadIdx.x >> 5);
    if (node >= NN) return;
    int lane = threadIdx.x & 31;
    float e = 1.0f + eps_ptr[layer];
    float4 sc4 = make_float4(1.f, 0.f, 0.f, 0.f), sh4 = sc4;
    if (HAS_T) {
        sc4 = *(const float4*)&tsc[lane * 4];
        sh4 = *(const float4*)&tsh[lane * 4];
    }
    int s = d_off[node], epos = d_off[node + 1];
    float4 acc = make_float4(0.f, 0.f, 0.f, 0.f);
    int j = s;
#pragma unroll 1
    for (; j + 4 <= epos; j += 4) {
        int i0 = d_csr[j], i1 = d_csr[j + 1], i2 = d_csr[j + 2], i3 = d_csr[j + 3];
        float4 v0 = act4<HAS_T>(*(const float4*)&xin[(size_t)i0 * ldx + lane * 4], sc4, sh4);
        float4 v1 = act4<HAS_T>(*(const float4*)&xin[(size_t)i1 * ldx + lane * 4], sc4, sh4);
        float4 v2 = act4<HAS_T>(*(const float4*)&xin[(size_t)i2 * ldx + lane * 4], sc4, sh4);
        float4 v3 = act4<HAS_T>(*(const float4*)&xin[(size_t)i3 * ldx + lane * 4], sc4, sh4);
        acc.x += (v0.x + v1.x) + (v2.x + v3.x);
        acc.y += (v0.y + v1.y) + (v2.y + v3.y);
        acc.z += (v0.z + v1.z) + (v2.z + v3.z);
        acc.w += (v0.w + v1.w) + (v2.w + v3.w);
    }
    for (; j < epos; ++j) {
        int i0 = d_csr[j];
        float4 v0 = act4<HAS_T>(*(const float4*)&xin[(size_t)i0 * ldx + lane * 4], sc4, sh4);
        acc.x += v0.x; acc.y += v0.y; acc.z += v0.z; acc.w += v0.w;
    }
    float4 xs = act4<HAS_T>(*(const float4*)&xin[(size_t)node * ldx + lane * 4], sc4, sh4);
    acc.x = fmaf(e, xs.x, acc.x); acc.y = fmaf(e, xs.y, acc.y);
    acc.z = fmaf(e, xs.z, acc.z); acc.w = fmaf(e, xs.w, acc.w);
    *(float4*)&u[(size_t)node * HH + lane * 4] = acc;
}

// ---------------- GEMM: Y = act(Ain) @ W^T + bias (bf16x3 HMMA), fused BN stats ----------------
template <bool HAS_T>
__global__ void __launch_bounds__(256, 1)
mm_hmma_kernel(const float* __restrict__ Ain, int lda,
               const float* __restrict__ tsc, const float* __restrict__ tsh,
               const __nv_bfloat16* __restrict__ Whi, const __nv_bfloat16* __restrict__ Wlo,
               const float* __restrict__ bias,
               float* __restrict__ Y, int ldy) {
    extern __shared__ char smem[];
    uint32_t sb = smem_u32(smem);
    int tid = threadIdx.x, wid = tid >> 5, lane = tid & 31;
    int row0 = blockIdx.x * 128;

    // W hi/lo -> smem (row n, col k, stride 136)
#pragma unroll
    for (int i = tid; i < 128 * 16; i += 256) {
        int r = i >> 4, c8 = (i & 15) * 8;
        uint32_t dsto = (uint32_t)(r * (TST * 2) + c8 * 2);
        *(uint4*)(smem + SM_WH + dsto) = *(const uint4*)&Whi[r * 128 + c8];
        *(uint4*)(smem + SM_WL + dsto) = *(const uint4*)&Wlo[r * 128 + c8];
    }

    // A: stream, optional scale/shift+relu, split to hi/lo smem
#pragma unroll 1
    for (int i = tid; i < 128 * 32; i += 256) {
        int r = i >> 5, c4 = (i & 31) * 4;
        int gr = row0 + r;
        float4 v = make_float4(0.f, 0.f, 0.f, 0.f);
        if (gr < NN) {
            v = *(const float4*)&Ain[(size_t)gr * lda + c4];
            if (HAS_T) {
                float4 sc4 = *(const float4*)&tsc[c4];
                float4 sh4 = *(const float4*)&tsh[c4];
                v = act4<true>(v, sc4, sh4);
            }
        }
        uint2 hi, lo;
        cvt_split4(v, hi, lo);
        uint32_t dsto = (uint32_t)(r * (TST * 2) + c4 * 2);
        *(uint2*)(smem + SM_AH + dsto) = hi;
        *(uint2*)(smem + SM_AL + dsto) = lo;
    }
    __syncthreads();

    // A fragments for this warp's 16 rows (all K)
    uint32_t ah[32], al[32];
    {
        int g = lane & 7, q = lane >> 3;
        uint32_t aaddr = sb + SM_AH + (uint32_t)((16 * wid + g + (q & 1) * 8) * (TST * 2) + (q >> 1) * 16);
#pragma unroll
        for (int k8 = 0; k8 < 8; k8++) {
            ldsm_x4(&ah[k8 * 4], aaddr + k8 * 32);
            ldsm_x4(&al[k8 * 4], aaddr + k8 * 32 + (SM_AL - SM_AH));
        }
    }
    __syncthreads();  // A smem reusable as staging

    // MMA: D = Ah*Wh + Al*Wh + Ah*Wl
    float* Ys = (float*)smem;
    {
        int g = lane & 7, q = (lane >> 3) & 1;
        uint32_t wbase = sb + SM_WH + (uint32_t)(g * (TST * 2) + q * 16);
        int gid = lane >> 2, ctib = lane & 3;
#pragma unroll 1
        for (int nt = 0; nt < 16; nt++) {
            float c[4] = {0.f, 0.f, 0.f, 0.f};
#pragma unroll
            for (int k8 = 0; k8 < 8; k8++) {
                uint32_t wa = wbase + (uint32_t)(nt * 8 * (TST * 2) + k8 * 32);
                uint32_t bh[2], bl[2];
                ldsm_x2(bh, wa);
                ldsm_x2(bl, wa + (SM_WL - SM_WH));
                mma_bf16(c, &ah[k8 * 4], bh);
                mma_bf16(c, &al[k8 * 4], bh);
                mma_bf16(c, &ah[k8 * 4], bl);
            }
            int col = nt * 8 + 2 * ctib;
            int r0w = 16 * wid + gid;
            Ys[r0w * YS_STRIDE + col] = c[0];
            Ys[r0w * YS_STRIDE + col + 1] = c[1];
            Ys[(r0w + 8) * YS_STRIDE + col] = c[2];
            Ys[(r0w + 8) * YS_STRIDE + col + 1] = c[3];
        }
    }
    __syncthreads();

    // epilogue: bias + coalesced store + fused BN stats
    {
        int c = tid & 127;
        float b = bias[c];
        float s = 0.f, s2 = 0.f;
        for (int rr = (tid >> 7); rr < 128; rr += 2) {
            int gr = row0 + rr;
            if (gr >= NN) break;
            float v = Ys[rr * YS_STRIDE + c] + b;
            s += v;
            s2 = fmaf(v, v, s2);
            Y[(size_t)gr * ldy + c] = v;
        }
        atomicAdd(&d_stats[c], s);
        atomicAdd(&d_stats[HH + c], s2);
    }
}

// ---------------- W conversion ----------------
__global__ void convw_kernel(const float* __restrict__ W1, const float* __restrict__ W2) {
    int i = blockIdx.x * 256 + threadIdx.x;
    if (i >= 8 * 16384) return;
    int mat = i >> 14, e = i & 16383, l = mat >> 1;
    float v = (mat & 1) ? W2[(size_t)l * 16384 + e] : W1[(size_t)l * 16384 + e];
    __nv_bfloat16 h = __float2bfloat16(v);
    d_Whi[i] = h;
    d_Wlo[i] = __float2bfloat16(v - __bfloat162float(h));
}

// ---------------- CSR build ----------------
__global__ void zero_deg_kernel() {
    int i = blockIdx.x * blockDim.x + threadIdx.x;
    if (i < NN) d_deg[i] = 0;
}
__global__ void count_kernel(const int* __restrict__ dst) {
    int i = blockIdx.x * blockDim.x + threadIdx.x;
    if (i < EE) atomicAdd(&d_deg[dst[i]], 1);
}
__global__ void scan_kernel() {
    __shared__ int wsum[32];
    __shared__ int carry_s;
    int t = threadIdx.x, lane = t & 31, w = t >> 5;
    if (t == 0) carry_s = 0;
    __syncthreads();
    for (int base = 0; base < NN; base += 1024) {
        int carry = carry_s;
        int idx = base + t;
        int v = (idx < NN) ? d_deg[idx] : 0;
        int x = v;
#pragma unroll
        for (int d = 1; d < 32; d <<= 1) {
            int y = __shfl_up_sync(0xffffffffu, x, d);
            if (lane >= d) x += y;
        }
        if (lane == 31) wsum[w] = x;
        __syncthreads();
        if (w == 0) {
            int s = wsum[lane];
#pragma unroll
            for (int d = 1; d < 32; d <<= 1) {
                int y = __shfl_up_sync(0xffffffffu, s, d);
                if (lane >= d) s += y;
            }
            wsum[lane] = s;
        }
        __syncthreads();
        int woff = (w > 0) ? wsum[w - 1] : 0;
        int excl = carry + woff + x - v;
        if (idx < NN) { d_off[idx] = excl; d_cursor[idx] = excl; }
        int tot = wsum[31];
        __syncthreads();
        if (t == 0) carry_s = carry + tot;
        __syncthreads();
    }
    if (threadIdx.x == 0) d_off[NN] = carry_s;
}
__global__ void fill_kernel(const int* __restrict__ src, const int* __restrict__ dst) {
    int i = blockIdx.x * blockDim.x + threadIdx.x;
    if (i < EE) {
        int p = atomicAdd(&d_cursor[dst[i]], 1);
        d_csr[p] = src[i];
    }
}

// ---------------- BN finalize (zeroes stats for next use) ----------------
__global__ void zero_stats_kernel() { d_stats[threadIdx.x] = 0.f; }

__global__ void bn_final_kernel(const float* __restrict__ gamma, const float* __restrict__ beta,
                                float* __restrict__ osc, float* __restrict__ osh) {
    int c = threadIdx.x;
    const float inv_n = 1.0f / (float)NN;
    float mu = d_stats[c] * inv_n;
    float var = fmaf(-mu, mu, d_stats[HH + c] * inv_n);
    float rinv = rsqrtf(var + 1e-5f);
    float sc = rinv * gamma[c];
    osc[c] = sc;
    osh[c] = fmaf(-mu, sc, beta[c]);
    d_stats[c] = 0.f;
    d_stats[HH + c] = 0.f;
}

// ---------------- pooling ----------------
__global__ void lower_bound_kernel(const int* __restrict__ seg, int n, int* __restrict__ out, int nseg) {
    int s = blockIdx.x * blockDim.x + threadIdx.x;
    if (s > nseg) return;
    int lo = 0, hi = n;
    while (lo < hi) {
        int mid = (lo + hi) >> 1;
        if (seg[mid] < s) lo = mid + 1; else hi = mid;
    }
    out[s] = lo;
}

__global__ void segmean_kernel(const float* __restrict__ in, const int* __restrict__ off,
                               float* __restrict__ out,
                               const float* __restrict__ tsc, const float* __restrict__ tsh) {
    int s = blockIdx.x, t = threadIdx.x;  // 128 threads, float4 each (512 cols)
    int r0 = off[s], r1 = off[s + 1];
    float4 sc4 = make_float4(1.f, 0.f, 0.f, 0.f), sh4 = sc4;
    bool hasT = (tsc != nullptr);
    if (hasT) { sc4 = *(const float4*)&tsc[t * 4]; sh4 = *(const float4*)&tsh[t * 4]; }
    float4 acc = make_float4(0.f, 0.f, 0.f, 0.f);
    for (int r = r0; r < r1; r++) {
        float4 v = *(const float4*)&in[(size_t)r * (LL * HH) + t * 4];
        if (hasT) {
            v.x = fmaxf(fmaf(v.x, sc4.x, sh4.x), 0.f);
            v.y = fmaxf(fmaf(v.y, sc4.y, sh4.y), 0.f);
            v.z = fmaxf(fmaf(v.z, sc4.z, sh4.z), 0.f);
            v.w = fmaxf(fmaf(v.w, sc4.w, sh4.w), 0.f);
        }
        acc.x += v.x; acc.y += v.y; acc.z += v.z; acc.w += v.w;
    }
    float inv = 1.0f / fmaxf((float)(r1 - r0), 1.0f);
    float4 o = make_float4(acc.x * inv, acc.y * inv, acc.z * inv, acc.w * inv);
    *(float4*)&out[(size_t)s * (LL * HH) + t * 4] = o;
}

// ---------------- head ----------------
__global__ void head_kernel(const float* __restrict__ gph,
                            const float* __restrict__ w1, const float* __restrict__ bb1,
                            const float* __restrict__ w2, const float* __restrict__ bb2,
                            float* __restrict__ out) {
    __shared__ float grow[LL * HH];
    __shared__ float hbuf[HH];
    __shared__ float obuf[CC];
    int g = blockIdx.x, t = threadIdx.x;
    for (int i = t; i < LL * HH; i += 128) grow[i] = gph[(size_t)g * (LL * HH) + i];
    __syncthreads();
    float acc = bb1[t];
#pragma unroll 8
    for (int k = 0; k < LL * HH; k++) acc = fmaf(grow[k], w1[(size_t)t * (LL * HH) + k], acc);
    hbuf[t] = fmaxf(acc, 0.f);
    __syncthreads();
    if (t < CC) {
        float a = bb2[t];
#pragma unroll 8
        for (int k = 0; k < HH; k++) a = fmaf(hbuf[k], w2[t * HH + k], a);
        obuf[t] = a;
    }
    __syncthreads();
    if (t == 0) {
        float m = obuf[0];
#pragma unroll
        for (int j = 1; j < CC; j++) m = fmaxf(m, obuf[j]);
        float se = 0.f;
#pragma unroll
        for (int j = 0; j < CC; j++) se += expf(obuf[j] - m);
        float lse = m + logf(se);
#pragma unroll
        for (int j = 0; j < CC; j++) out[g * CC + j] = obuf[j] - lse;
    }
}

// ---------------- launcher ----------------
extern "C" void kernel_launch(void* const* d_in, const int* in_sizes, int n_in,
                              void* d_out, int out_size) {
    const float* x     = (const float*)d_in[0];
    const int*   ei    = (const int*)d_in[1];
    const int*   n2s   = (const int*)d_in[2];
    const int*   s2g   = (const int*)d_in[3];
    const float* W1    = (const float*)d_in[4];
    const float* b1    = (const float*)d_in[5];
    const float* g1    = (const float*)d_in[6];
    const float* be1   = (const float*)d_in[7];
    const float* W2    = (const float*)d_in[8];
    const float* b2    = (const float*)d_in[9];
    const float* g2    = (const float*)d_in[10];
    const float* be2   = (const float*)d_in[11];
    const float* eps   = (const float*)d_in[12];
    const float* lin1W = (const float*)d_in[13];
    const float* lin1b = (const float*)d_in[14];
    const float* lin2W = (const float*)d_in[15];
    const float* lin2b = (const float*)d_in[16];
    float* out = (float*)d_out;

    void* p;
    cudaGetSymbolAddress(&p, d_u);      float* up      = (float*)p;
    cudaGetSymbolAddress(&p, d_t);      float* tp      = (float*)p;
    cudaGetSymbolAddress(&p, d_feat);   float* featp   = (float*)p;
    cudaGetSymbolAddress(&p, d_sc1);    float* sc1p    = (float*)p;
    cudaGetSymbolAddress(&p, d_sh1);    float* sh1p    = (float*)p;
    cudaGetSymbolAddress(&p, d_pscale); float* pscp    = (float*)p;
    cudaGetSymbolAddress(&p, d_pshift); float* pshp    = (float*)p;
    cudaGetSymbolAddress(&p, d_sub);    float* subp    = (float*)p;
    cudaGetSymbolAddress(&p, d_gph);    float* gphp    = (float*)p;
    cudaGetSymbolAddress(&p, d_suboff); int* suboffp   = (int*)p;
    cudaGetSymbolAddress(&p, d_gphoff); int* gphoffp   = (int*)p;
    cudaGetSymbolAddress(&p, d_Whi);    __nv_bfloat16* whip = (__nv_bfloat16*)p;
    cudaGetSymbolAddress(&p, d_Wlo);    __nv_bfloat16* wlop = (__nv_bfloat16*)p;

    cudaFuncSetAttribute(mm_hmma_kernel<false>, cudaFuncAttributeMaxDynamicSharedMemorySize, MM_SMEM);
    cudaFuncSetAttribute(mm_hmma_kernel<true>,  cudaFuncAttributeMaxDynamicSharedMemorySize, MM_SMEM);

    const int* src = ei;
    const int* dst = ei + EE;

    zero_stats_kernel<<<1, 2 * HH>>>();
    convw_kernel<<<(8 * 16384 + 255) / 256, 256>>>(W1, W2);

    zero_deg_kernel<<<(NN + 255) / 256, 256>>>();
    count_kernel<<<(EE + 255) / 256, 256>>>(dst);
    scan_kernel<<<1, 1024>>>();
    fill_kernel<<<(EE + 255) / 256, 256>>>(src, dst);

    const int tiles = (NN + 127) / 128;
    const int agg_blocks = (NN + 7) / 8;
    for (int l = 0; l < LL; l++) {
        const __nv_bfloat16* whi1 = whip + (size_t)(l * 2) * 16384;
        const __nv_bfloat16* wlo1 = wlop + (size_t)(l * 2) * 16384;
        const __nv_bfloat16* whi2 = whip + (size_t)(l * 2 + 1) * 16384;
        const __nv_bfloat16* wlo2 = wlop + (size_t)(l * 2 + 1) * 16384;

        // aggregate (BN2+ReLU of previous layer fused into the read)
        if (l == 0) {
            agg_kernel<false><<<agg_blocks, 256>>>(x, FF, nullptr, nullptr, eps, 0, up);
        } else {
            agg_kernel<true><<<agg_blocks, 256>>>(
                featp + (size_t)(l - 1) * HH, LL * HH,
                pscp + (size_t)(l - 1) * HH, pshp + (size_t)(l - 1) * HH, eps, l, up);
        }

        // MLP linear 1 (no input transform) + fused stats
        mm_hmma_kernel<false><<<tiles, 256, MM_SMEM>>>(
            up, HH, nullptr, nullptr, whi1, wlo1, b1 + (size_t)l * HH, tp, HH);
        bn_final_kernel<<<1, HH>>>(g1 + (size_t)l * HH, be1 + (size_t)l * HH, sc1p, sh1p);

        // MLP linear 2 (BN1+ReLU fused into input) + fused stats -> raw z in feat slot
        mm_hmma_kernel<true><<<tiles, 256, MM_SMEM>>>(
            tp, HH, sc1p, sh1p, whi2, wlo2, b2 + (size_t)l * HH,
            featp + (size_t)l * HH, LL * HH);
        bn_final_kernel<<<1, HH>>>(g2 + (size_t)l * HH, be2 + (size_t)l * HH,
                                   pscp + (size_t)l * HH, pshp + (size_t)l * HH);
    }

    lower_bound_kernel<<<(SS + 1 + 255) / 256, 256>>>(n2s, NN, suboffp, SS);
    lower_bound_kernel<<<(GG + 1 + 255) / 256, 256>>>(s2g, SS, gphoffp, GG);
    segmean_kernel<<<SS, 128>>>(featp, suboffp, subp, pscp, pshp);
    segmean_kernel<<<GG, 128>>>(subp, gphoffp, gphp, nullptr, nullptr);

    head_kernel<<<GG, 128>>>(gphp, lin1W, lin1b, lin2W, lin2b, out);
}